// round 5
// baseline (speedup 1.0000x reference)
#include <cuda_runtime.h>
#include <cstdint>
#include <cstddef>

// ---------------------------------------------------------------------------
// MultiDimHiPPO2 on sm_100 (non-'a' PTX target: NO tcgen05; legacy mma.sync).
//
//   out[b, f, m] = base[b, f, m] + sum_k T[f,k] * slice[b,k,m]
//   T[f,k] = cos(2pi*(k+tok)*f/8192)        for f in [0,512)
//          = sin(2pi*(k+tok)*(f-512)/8192)  for f in [512,1024)
//
// Operands pre-shuffled into exact m16n8k8 tf32 fragment order; GEMM mainloop
// is pure coalesced LDG.128 + HMMA with distance-16 L2 prefetch.
// ---------------------------------------------------------------------------

#define KDIM    4096
#define MDIM    1024
#define FDIM    1024
#define NSTEP   (KDIM / 8)        // 512 k-steps of 8
#define PFD     16                // L2 prefetch distance (k-steps)

// A-fragment store:  Afrag[(rb16*512 + s)*32 + lane] = {a0,a1,a2,a3}
__device__ float4 Afrag[64 * NSTEP * 32];                 // 16 MB

// B-fragment store:  Bfrag[(((b*512+s)*16 + nb)*4 + q)*32 + lane]
__device__ float4 Bfrag[4 * NSTEP * 16 * 4 * 32];         // 64 MB

__device__ __forceinline__ uint32_t f2tf32(float x) {
    uint32_t r;
    asm("cvt.rna.tf32.f32 %0, %1;" : "=r"(r) : "f"(x));
    return r;
}
__device__ __forceinline__ float tf32f(float x) {
    return __uint_as_float(f2tf32(x));
}

// exact integer phase -> trig value (tf32-rounded)
__device__ __forceinline__ float trigval(int k, int tok, int n, bool use_sin) {
    int p = ((k + tok) * n) & 8191;
    if (p >= 4096) p -= 8192;
    float ang = (float)p * (6.28318530718f / 8192.0f);
    float v = use_sin ? __sinf(ang) : __cosf(ang);
    return tf32f(v);
}

// ---------------- kernel 1: merged pre-pass ----------------
// blocks [0,4096): trig table in A-frag order (1M float4)
// blocks [4096,8192): slice shuffle into B-frag order (1M threads x 4 float4)
__global__ void __launch_bounds__(256) prep_kernel(const int* __restrict__ tokp,
                                                   const float* __restrict__ slice)
{
    if (blockIdx.x < 4096) {
        int t = blockIdx.x * 256 + threadIdx.x;        // 0 .. 1M-1
        int lane = t & 31;
        int s    = (t >> 5) & 511;
        int rb16 = t >> 14;                            // 0..63
        int g   = lane >> 2;
        int tig = lane & 3;
        int token = tokp ? tokp[0] : 1024;

        int f1 = rb16 * 16 + g;
        int f2 = f1 + 8;
        bool use_sin = (f1 >= 512);
        int n1 = f1 & 511;
        int n2 = f2 & 511;
        int k1 = s * 8 + tig;
        int k2 = k1 + 4;

        float4 v;
        v.x = trigval(k1, token, n1, use_sin);
        v.y = trigval(k1, token, n2, use_sin);
        v.z = trigval(k2, token, n1, use_sin);
        v.w = trigval(k2, token, n2, use_sin);
        Afrag[t] = v;
    } else {
        int t = (blockIdx.x - 4096) * 256 + threadIdx.x;  // 0 .. 1M-1
        int lane = t & 31;
        int nb   = (t >> 5) & 15;
        int s    = (t >> 9) & 511;
        int b    = t >> 18;
        int g   = lane >> 2;
        int tig = lane & 3;

        const float* sp = slice + ((size_t)b * KDIM) * MDIM + nb * 64 + g;
        float v[8][2];
        #pragma unroll
        for (int h = 0; h < 2; h++) {
            int k = s * 8 + tig + 4 * h;
            const float* rp = sp + (size_t)k * MDIM;
            #pragma unroll
            for (int j = 0; j < 8; j++) v[j][h] = __ldg(rp + j * 8);
        }
        float4* dst = Bfrag + ((size_t)((b * 512 + s) * 16 + nb) * 4) * 32 + lane;
        #pragma unroll
        for (int q = 0; q < 4; q++) {
            float4 o;
            o.x = tf32f(v[2 * q    ][0]);
            o.y = tf32f(v[2 * q    ][1]);
            o.z = tf32f(v[2 * q + 1][0]);
            o.w = tf32f(v[2 * q + 1][1]);
            dst[q * 32] = o;
        }
    }
}

// ---------------- kernel 2: the GEMM ----------------
#define MMA4(acc, av, b0, b1)                                                   \
    asm volatile(                                                               \
        "mma.sync.aligned.m16n8k8.row.col.f32.tf32.tf32.f32 "                   \
        "{%0,%1,%2,%3}, {%4,%5,%6,%7}, {%8,%9}, {%0,%1,%2,%3};\n"               \
        : "+f"((acc)[0]), "+f"((acc)[1]), "+f"((acc)[2]), "+f"((acc)[3])        \
        : "r"(__float_as_uint((av).x)), "r"(__float_as_uint((av).y)),           \
          "r"(__float_as_uint((av).z)), "r"(__float_as_uint((av).w)),           \
          "r"(__float_as_uint(b0)), "r"(__float_as_uint(b1)))

#define PF_L2(p) asm volatile("prefetch.global.L2 [%0];" :: "l"(p))

__global__ void __launch_bounds__(256, 1) hippo_gemm(
    const float* __restrict__ base,
    float*       __restrict__ out)
{
    const int tid  = threadIdx.x;
    const int warp = tid >> 5;
    const int lane = tid & 31;
    const int g    = lane >> 2;
    const int tig  = lane & 3;

    const int mb = blockIdx.x;            // 0..3   (256 m per CTA)
    const int fb = blockIdx.y;            // 0..7   (128 freq per CTA)
    const int b  = blockIdx.z;

    const int warp_f = warp & 1;          // 2 freq halves of 64
    const int warp_n = warp >> 1;         // 4 m-chunks of 64
    const int rbg0 = fb * 8 + warp_f * 4; // first 16-row block of this warp
    const int nbg  = mb * 4 + warp_n;     // 64-m block id (0..15)

    const float4* Ap = Afrag + ((size_t)rbg0 * NSTEP) * 32 + lane;
    const float4* Bp = Bfrag + ((size_t)(b * NSTEP) * 16 + nbg) * 4 * 32 + lane;

    float acc[4][8][4];
    #pragma unroll
    for (int rb = 0; rb < 4; rb++)
        #pragma unroll
        for (int j = 0; j < 8; j++)
            #pragma unroll
            for (int c = 0; c < 4; c++) acc[rb][j][c] = 0.f;

    // warm L2 for the first PFD steps
    #pragma unroll
    for (int s = 2; s < PFD; s += 2) {
        #pragma unroll
        for (int rb = 0; rb < 4; rb++) PF_L2(Ap + (size_t)s * 32 + rb * (NSTEP * 32));
        #pragma unroll
        for (int q = 0; q < 4; q++)    PF_L2(Bp + (size_t)s * 2048 + q * 32);
    }

    float4 ab[2][4], bb[2][4];
    #pragma unroll
    for (int rb = 0; rb < 4; rb++) ab[0][rb] = __ldg(Ap + rb * (NSTEP * 32));
    #pragma unroll
    for (int q = 0; q < 4; q++)    bb[0][q]  = __ldg(Bp + q * 32);

    #pragma unroll 1
    for (int s = 0; s < NSTEP; s += 2) {
        // prefetch s+1 into buf 1
        {
            const float4* Apn = Ap + (size_t)(s + 1) * 32;
            const float4* Bpn = Bp + (size_t)(s + 1) * 2048;
            #pragma unroll
            for (int rb = 0; rb < 4; rb++) ab[1][rb] = __ldg(Apn + rb * (NSTEP * 32));
            #pragma unroll
            for (int q = 0; q < 4; q++)    bb[1][q]  = __ldg(Bpn + q * 32);
        }
        // L2 prefetch for step s+PFD
        if (s + PFD < NSTEP) {
            const float4* Apf = Ap + (size_t)(s + PFD) * 32;
            const float4* Bpf = Bp + (size_t)(s + PFD) * 2048;
            #pragma unroll
            for (int rb = 0; rb < 4; rb++) PF_L2(Apf + rb * (NSTEP * 32));
            #pragma unroll
            for (int q = 0; q < 4; q++)    PF_L2(Bpf + q * 32);
        }
        // mma on buf 0
        #pragma unroll
        for (int rb = 0; rb < 4; rb++)
            #pragma unroll
            for (int j = 0; j < 8; j++) {
                const float4& bq = bb[0][j >> 1];
                if (j & 1) { MMA4(acc[rb][j], ab[0][rb], bq.z, bq.w); }
                else       { MMA4(acc[rb][j], ab[0][rb], bq.x, bq.y); }
            }
        // prefetch s+2 into buf 0
        if (s + 2 < NSTEP) {
            const float4* Apn = Ap + (size_t)(s + 2) * 32;
            const float4* Bpn = Bp + (size_t)(s + 2) * 2048;
            #pragma unroll
            for (int rb = 0; rb < 4; rb++) ab[0][rb] = __ldg(Apn + rb * (NSTEP * 32));
            #pragma unroll
            for (int q = 0; q < 4; q++)    bb[0][q]  = __ldg(Bpn + q * 32);
        }
        // L2 prefetch for step s+PFD+1
        if (s + PFD + 1 < NSTEP) {
            const float4* Apf = Ap + (size_t)(s + PFD + 1) * 32;
            const float4* Bpf = Bp + (size_t)(s + PFD + 1) * 2048;
            #pragma unroll
            for (int rb = 0; rb < 4; rb++) PF_L2(Apf + rb * (NSTEP * 32));
            #pragma unroll
            for (int q = 0; q < 4; q++)    PF_L2(Bpf + q * 32);
        }
        // mma on buf 1
        #pragma unroll
        for (int rb = 0; rb < 4; rb++)
            #pragma unroll
            for (int j = 0; j < 8; j++) {
                const float4& bq = bb[1][j >> 1];
                if (j & 1) { MMA4(acc[rb][j], ab[1][rb], bq.z, bq.w); }
                else       { MMA4(acc[rb][j], ab[1][rb], bq.x, bq.y); }
            }
    }

    // ---- epilogue: out = base + acc
    const int col0 = mb * 256 + warp_n * 64 + tig * 2;
    #pragma unroll
    for (int rb = 0; rb < 4; rb++) {
        int r0 = (rbg0 + rb) * 16 + g;
        size_t off0 = ((size_t)(b * FDIM + r0)) * MDIM + col0;
        size_t off1 = off0 + (size_t)8 * MDIM;
        #pragma unroll
        for (int j = 0; j < 8; j++) {
            size_t o0 = off0 + j * 8;
            size_t o1 = off1 + j * 8;
            float2 b0 = *(const float2*)(base + o0);
            float2 b1 = *(const float2*)(base + o1);
            float2 w0, w1;
            w0.x = b0.x + acc[rb][j][0];
            w0.y = b0.y + acc[rb][j][1];
            w1.x = b1.x + acc[rb][j][2];
            w1.y = b1.y + acc[rb][j][3];
            *(float2*)(out + o0) = w0;
            *(float2*)(out + o1) = w1;
        }
    }
}

// ---------------- host launch ----------------
extern "C" void kernel_launch(void* const* d_in, const int* in_sizes, int n_in,
                              void* d_out, int out_size)
{
    const float* base  = nullptr;
    const float* slice = nullptr;
    const int*   tok   = nullptr;
    for (int i = 0; i < n_in; i++) {
        if      (in_sizes[i] == 4 * 4096 * 1024) slice = (const float*)d_in[i];
        else if (in_sizes[i] == 4 * 1024 * 1024) base  = (const float*)d_in[i];
        else                                     tok   = (const int*)d_in[i];
    }
    if (!base  && n_in > 0) base  = (const float*)d_in[0];
    if (!slice && n_in > 1) slice = (const float*)d_in[1];

    prep_kernel<<<8192, 256>>>(tok, slice);

    dim3 grid(4, 8, 4);   // m-blocks(256) x f-blocks(128) x batch = 128 CTAs
    hippo_gemm<<<grid, 256>>>(base, (float*)d_out);
}

// round 6
// speedup vs baseline: 1.0303x; 1.0303x over previous
#include <cuda_runtime.h>
#include <cstdint>
#include <cstddef>

// ---------------------------------------------------------------------------
// MultiDimHiPPO2 on sm_100 (non-'a' PTX target: NO tcgen05; legacy mma.sync).
//
//   out[b, f, m] = base[b, f, m] + sum_k T[f,k] * slice[b,k,m]
//   T[f,k] = cos(2pi*(k+tok)*f/8192)        for f in [0,512)
//          = sin(2pi*(k+tok)*(f-512)/8192)  for f in [512,1024)
//
// Operands pre-shuffled into exact m16n8k8 tf32 fragment order in gmem.
// GEMM: 5-stage cp.async smem pipeline (16 k / stage) -> conflict-free
// ld.shared.v4 fragment loads -> HMMA. Latency hiding no longer costs regs.
// ---------------------------------------------------------------------------

#define KDIM    4096
#define MDIM    1024
#define FDIM    1024
#define NSTEP   (KDIM / 8)        // 512 k-steps of 8
#define NITER   (NSTEP / 2)       // 256 stages of 16 k
#define STAGES  5
#define STAGE_A_BYTES 8192        // 128 f x 16 k x 4B (frag order)
#define STAGE_B_BYTES 16384       // 256 m x 16 k x 4B (frag order)
#define STAGE_BYTES   (STAGE_A_BYTES + STAGE_B_BYTES)   // 24 KB
#define SMEM_TOTAL    (STAGES * STAGE_BYTES)            // 120 KB

// A-fragment store:  Afrag[(rb16*512 + s)*32 + lane] = {a0,a1,a2,a3}
__device__ float4 Afrag[64 * NSTEP * 32];                 // 16 MB
// B-fragment store:  Bfrag[(((b*512+s)*16 + nb)*4 + q)*32 + lane]
__device__ float4 Bfrag[4 * NSTEP * 16 * 4 * 32];         // 64 MB

__device__ __forceinline__ uint32_t f2tf32(float x) {
    uint32_t r;
    asm("cvt.rna.tf32.f32 %0, %1;" : "=r"(r) : "f"(x));
    return r;
}
__device__ __forceinline__ float tf32f(float x) {
    return __uint_as_float(f2tf32(x));
}
__device__ __forceinline__ uint32_t smem_u32(const void* p) {
    uint32_t a;
    asm("{ .reg .u64 t; cvta.to.shared.u64 t, %1; cvt.u32.u64 %0, t; }"
        : "=r"(a) : "l"(p));
    return a;
}

// exact integer phase -> trig value (tf32-rounded)
__device__ __forceinline__ float trigval(int k, int tok, int n, bool use_sin) {
    int p = ((k + tok) * n) & 8191;
    if (p >= 4096) p -= 8192;
    float ang = (float)p * (6.28318530718f / 8192.0f);
    float v = use_sin ? __sinf(ang) : __cosf(ang);
    return tf32f(v);
}

// ---------------- kernel 1: merged pre-pass ----------------
__global__ void __launch_bounds__(256) prep_kernel(const int* __restrict__ tokp,
                                                   const float* __restrict__ slice)
{
    if (blockIdx.x < 4096) {
        int t = blockIdx.x * 256 + threadIdx.x;        // 0 .. 1M-1
        int lane = t & 31;
        int s    = (t >> 5) & 511;
        int rb16 = t >> 14;                            // 0..63
        int g   = lane >> 2;
        int tig = lane & 3;
        int token = tokp ? tokp[0] : 1024;

        int f1 = rb16 * 16 + g;
        int f2 = f1 + 8;
        bool use_sin = (f1 >= 512);
        int n1 = f1 & 511;
        int n2 = f2 & 511;
        int k1 = s * 8 + tig;
        int k2 = k1 + 4;

        float4 v;
        v.x = trigval(k1, token, n1, use_sin);
        v.y = trigval(k1, token, n2, use_sin);
        v.z = trigval(k2, token, n1, use_sin);
        v.w = trigval(k2, token, n2, use_sin);
        Afrag[t] = v;
    } else {
        int t = (blockIdx.x - 4096) * 256 + threadIdx.x;  // 0 .. 1M-1
        int lane = t & 31;
        int nb   = (t >> 5) & 15;
        int s    = (t >> 9) & 511;
        int b    = t >> 18;
        int g   = lane >> 2;
        int tig = lane & 3;

        const float* sp = slice + ((size_t)b * KDIM) * MDIM + nb * 64 + g;
        float v[8][2];
        #pragma unroll
        for (int h = 0; h < 2; h++) {
            int k = s * 8 + tig + 4 * h;
            const float* rp = sp + (size_t)k * MDIM;
            #pragma unroll
            for (int j = 0; j < 8; j++) v[j][h] = rp[j * 8];
        }
        float4* dst = Bfrag + ((size_t)((b * 512 + s) * 16 + nb) * 4) * 32 + lane;
        #pragma unroll
        for (int q = 0; q < 4; q++) {
            float4 o;
            o.x = tf32f(v[2 * q    ][0]);
            o.y = tf32f(v[2 * q    ][1]);
            o.z = tf32f(v[2 * q + 1][0]);
            o.w = tf32f(v[2 * q + 1][1]);
            dst[q * 32] = o;
        }
    }
}

// ---------------- kernel 2: the GEMM ----------------
#define MMA4(acc, av, b0, b1)                                                   \
    asm volatile(                                                               \
        "mma.sync.aligned.m16n8k8.row.col.f32.tf32.tf32.f32 "                   \
        "{%0,%1,%2,%3}, {%4,%5,%6,%7}, {%8,%9}, {%0,%1,%2,%3};\n"               \
        : "+f"((acc)[0]), "+f"((acc)[1]), "+f"((acc)[2]), "+f"((acc)[3])        \
        : "r"(__float_as_uint((av).x)), "r"(__float_as_uint((av).y)),           \
          "r"(__float_as_uint((av).z)), "r"(__float_as_uint((av).w)),           \
          "r"(__float_as_uint(b0)), "r"(__float_as_uint(b1)))

#define CPA16(dst, src)                                                         \
    asm volatile("{ .reg .u64 g; cvta.to.global.u64 g, %1;"                     \
                 "  cp.async.cg.shared.global [%0], [g], 16; }"                 \
                 :: "r"(dst), "l"(src) : "memory")
#define CP_COMMIT() asm volatile("cp.async.commit_group;" ::: "memory")
#define CP_WAIT3()  asm volatile("cp.async.wait_group 3;" ::: "memory")

#define LDS128F(v, addr)                                                        \
    asm volatile("ld.shared.v4.f32 {%0,%1,%2,%3}, [%4];"                        \
                 : "=f"((v).x), "=f"((v).y), "=f"((v).z), "=f"((v).w)           \
                 : "r"(addr))

// issue cp.async copies for pipeline stage i into smem slot
__device__ __forceinline__ void issue_stage(uint32_t sbase, int slot, int i,
                                            int fb, int mb, int b, int tid)
{
    uint32_t sa = sbase + slot * STAGE_BYTES;
    uint32_t sbB = sa + STAGE_A_BYTES;
    // A: 512 float4 (2 substeps x 8 rb x 32 lane), 2 per thread
    #pragma unroll
    for (int j = 0; j < 2; j++) {
        int c    = tid + 256 * j;
        int ss   = c >> 8;
        int rb   = (c >> 5) & 7;
        int lane = c & 31;
        const float4* src = Afrag + ((size_t)(fb * 8 + rb) * NSTEP + (2 * i + ss)) * 32 + lane;
        CPA16(sa + c * 16, src);
    }
    // B: 1024 float4 (2 substeps x 512), 4 per thread
    #pragma unroll
    for (int j = 0; j < 4; j++) {
        int c   = tid + 256 * j;
        int ss  = c >> 9;
        int rem = c & 511;
        const float4* src = Bfrag + ((size_t)((b * NSTEP + 2 * i + ss) * 16 + mb * 4)) * 128 + rem;
        CPA16(sbB + c * 16, src);
    }
}

__global__ void __launch_bounds__(256, 1) hippo_gemm(
    const float* __restrict__ base,
    float*       __restrict__ out)
{
    extern __shared__ char smem_raw[];
    const uint32_t sbase = smem_u32(smem_raw);

    const int tid  = threadIdx.x;
    const int warp = tid >> 5;
    const int lane = tid & 31;
    const int g    = lane >> 2;
    const int tig  = lane & 3;

    const int mb = blockIdx.x;            // 0..3   (256 m per CTA)
    const int fb = blockIdx.y;            // 0..7   (128 freq per CTA)
    const int b  = blockIdx.z;

    const int warp_f = warp & 1;          // 2 freq halves of 64
    const int warp_n = warp >> 1;         // 4 m-chunks of 64
    const int rbg0 = fb * 8 + warp_f * 4; // first 16-row block of this warp

    float acc[4][8][4];
    #pragma unroll
    for (int rb = 0; rb < 4; rb++)
        #pragma unroll
        for (int j = 0; j < 8; j++)
            #pragma unroll
            for (int c = 0; c < 4; c++) acc[rb][j][c] = 0.f;

    // ---- prologue: fill stages 0..3
    #pragma unroll
    for (int i = 0; i < STAGES - 1; i++) {
        issue_stage(sbase, i, i, fb, mb, b, tid);
        CP_COMMIT();
    }

    // per-warp smem fragment bases (slot-relative)
    const uint32_t a_off = warp_f * 2048 + lane * 16;               // + ss*4096 + rb*512
    const uint32_t b_off = STAGE_A_BYTES + warp_n * 2048 + lane * 16; // + ss*8192 + q*512

    #pragma unroll 1
    for (int i = 0; i < NITER; i++) {
        CP_WAIT3();            // stage i arrived
        __syncthreads();       // all warps done reading slot being overwritten

        if (i + STAGES - 1 < NITER)
            issue_stage(sbase, (i + STAGES - 1) % STAGES, i + STAGES - 1, fb, mb, b, tid);
        CP_COMMIT();           // always commit (empty groups complete instantly)

        const uint32_t slot_base = sbase + (i % STAGES) * STAGE_BYTES;

        #pragma unroll
        for (int ss = 0; ss < 2; ss++) {
            float4 ab[4], bq[4];
            uint32_t ab_addr = slot_base + a_off + ss * 4096;
            uint32_t bb_addr = slot_base + b_off + ss * 8192;
            #pragma unroll
            for (int rb = 0; rb < 4; rb++) LDS128F(ab[rb], ab_addr + rb * 512);
            #pragma unroll
            for (int q = 0; q < 4; q++)    LDS128F(bq[q], bb_addr + q * 512);

            #pragma unroll
            for (int rb = 0; rb < 4; rb++)
                #pragma unroll
                for (int j = 0; j < 8; j++) {
                    const float4& bv = bq[j >> 1];
                    if (j & 1) { MMA4(acc[rb][j], ab[rb], bv.z, bv.w); }
                    else       { MMA4(acc[rb][j], ab[rb], bv.x, bv.y); }
                }
        }
    }

    // ---- epilogue: out = base + acc
    const int col0 = mb * 256 + warp_n * 64 + tig * 2;
    #pragma unroll
    for (int rb = 0; rb < 4; rb++) {
        int r0 = (rbg0 + rb) * 16 + g;
        size_t off0 = ((size_t)(b * FDIM + r0)) * MDIM + col0;
        size_t off1 = off0 + (size_t)8 * MDIM;
        #pragma unroll
        for (int j = 0; j < 8; j++) {
            size_t o0 = off0 + j * 8;
            size_t o1 = off1 + j * 8;
            float2 b0 = *(const float2*)(base + o0);
            float2 b1 = *(const float2*)(base + o1);
            float2 w0, w1;
            w0.x = b0.x + acc[rb][j][0];
            w0.y = b0.y + acc[rb][j][1];
            w1.x = b1.x + acc[rb][j][2];
            w1.y = b1.y + acc[rb][j][3];
            *(float2*)(out + o0) = w0;
            *(float2*)(out + o1) = w1;
        }
    }
}

// ---------------- host launch ----------------
extern "C" void kernel_launch(void* const* d_in, const int* in_sizes, int n_in,
                              void* d_out, int out_size)
{
    const float* base  = nullptr;
    const float* slice = nullptr;
    const int*   tok   = nullptr;
    for (int i = 0; i < n_in; i++) {
        if      (in_sizes[i] == 4 * 4096 * 1024) slice = (const float*)d_in[i];
        else if (in_sizes[i] == 4 * 1024 * 1024) base  = (const float*)d_in[i];
        else                                     tok   = (const int*)d_in[i];
    }
    if (!base  && n_in > 0) base  = (const float*)d_in[0];
    if (!slice && n_in > 1) slice = (const float*)d_in[1];

    static bool attr_set = false;
    if (!attr_set) {
        cudaFuncSetAttribute(hippo_gemm,
                             cudaFuncAttributeMaxDynamicSharedMemorySize, SMEM_TOTAL);
        attr_set = true;
    }

    prep_kernel<<<8192, 256>>>(tok, slice);

    dim3 grid(4, 8, 4);   // m-blocks(256) x f-blocks(128) x batch = 128 CTAs
    hippo_gemm<<<grid, 256, SMEM_TOTAL>>>(base, (float*)d_out);
}

// round 7
// speedup vs baseline: 1.0387x; 1.0081x over previous
#include <cuda_runtime.h>
#include <cstdint>
#include <cstddef>

// ---------------------------------------------------------------------------
// MultiDimHiPPO2 on sm_100 (non-'a' PTX target: NO tcgen05; legacy mma.sync).
//
//   out[b, f, m] = base[b, f, m] + sum_k T[f,k] * slice[b,k,m]
//   T[f,k] = cos(2pi*(k+tok)*f/8192)        for f in [0,512)
//          = sin(2pi*(k+tok)*(f-512)/8192)  for f in [512,1024)
//
// Operands pre-shuffled into m16n8k8 tf32 fragment order in gmem.
// GEMM: 512 threads (16 warps -> 4/SMSP), warp tile 64x32 (acc=64 regs),
// 5-stage cp.async smem pipeline, conflict-free ld.shared.v4 frag loads.
// ---------------------------------------------------------------------------

#define KDIM    4096
#define MDIM    1024
#define FDIM    1024
#define NSTEP   (KDIM / 8)        // 512 k-steps of 8
#define NITER   (NSTEP / 2)       // 256 stages of 16 k
#define STAGES  5
#define STAGE_A_BYTES 8192        // 128 f x 16 k x 4B (frag order)
#define STAGE_B_BYTES 16384       // 256 m x 16 k x 4B (frag order)
#define STAGE_BYTES   (STAGE_A_BYTES + STAGE_B_BYTES)   // 24 KB
#define SMEM_TOTAL    (STAGES * STAGE_BYTES)            // 120 KB

// A-fragment store:  Afrag[(rb16*512 + s)*32 + lane] = {a0,a1,a2,a3}
__device__ float4 Afrag[64 * NSTEP * 32];                 // 16 MB
// B-fragment store:  Bfrag[(((b*512+s)*16 + nb)*4 + q)*32 + lane]
__device__ float4 Bfrag[4 * NSTEP * 16 * 4 * 32];         // 64 MB

__device__ __forceinline__ uint32_t f2tf32(float x) {
    uint32_t r;
    asm("cvt.rna.tf32.f32 %0, %1;" : "=r"(r) : "f"(x));
    return r;
}
__device__ __forceinline__ float tf32f(float x) {
    return __uint_as_float(f2tf32(x));
}
__device__ __forceinline__ uint32_t smem_u32(const void* p) {
    uint32_t a;
    asm("{ .reg .u64 t; cvta.to.shared.u64 t, %1; cvt.u32.u64 %0, t; }"
        : "=r"(a) : "l"(p));
    return a;
}

// exact integer phase -> trig value (tf32-rounded)
__device__ __forceinline__ float trigval(int k, int tok, int n, bool use_sin) {
    int p = ((k + tok) * n) & 8191;
    if (p >= 4096) p -= 8192;
    float ang = (float)p * (6.28318530718f / 8192.0f);
    float v = use_sin ? __sinf(ang) : __cosf(ang);
    return tf32f(v);
}

// ---------------- kernel 1: merged pre-pass ----------------
__global__ void __launch_bounds__(256) prep_kernel(const int* __restrict__ tokp,
                                                   const float* __restrict__ slice)
{
    if (blockIdx.x < 4096) {
        int t = blockIdx.x * 256 + threadIdx.x;        // 0 .. 1M-1
        int lane = t & 31;
        int s    = (t >> 5) & 511;
        int rb16 = t >> 14;                            // 0..63
        int g   = lane >> 2;
        int tig = lane & 3;
        int token = tokp ? tokp[0] : 1024;

        int f1 = rb16 * 16 + g;
        int f2 = f1 + 8;
        bool use_sin = (f1 >= 512);
        int n1 = f1 & 511;
        int n2 = f2 & 511;
        int k1 = s * 8 + tig;
        int k2 = k1 + 4;

        float4 v;
        v.x = trigval(k1, token, n1, use_sin);
        v.y = trigval(k1, token, n2, use_sin);
        v.z = trigval(k2, token, n1, use_sin);
        v.w = trigval(k2, token, n2, use_sin);
        Afrag[t] = v;
    } else {
        int t = (blockIdx.x - 4096) * 256 + threadIdx.x;  // 0 .. 1M-1
        int lane = t & 31;
        int nb   = (t >> 5) & 15;
        int s    = (t >> 9) & 511;
        int b    = t >> 18;
        int g   = lane >> 2;
        int tig = lane & 3;

        const float* sp = slice + ((size_t)b * KDIM) * MDIM + nb * 64 + g;
        float v[8][2];
        #pragma unroll
        for (int h = 0; h < 2; h++) {
            int k = s * 8 + tig + 4 * h;
            const float* rp = sp + (size_t)k * MDIM;
            #pragma unroll
            for (int j = 0; j < 8; j++) v[j][h] = rp[j * 8];
        }
        float4* dst = Bfrag + ((size_t)((b * 512 + s) * 16 + nb) * 4) * 32 + lane;
        #pragma unroll
        for (int q = 0; q < 4; q++) {
            float4 o;
            o.x = tf32f(v[2 * q    ][0]);
            o.y = tf32f(v[2 * q    ][1]);
            o.z = tf32f(v[2 * q + 1][0]);
            o.w = tf32f(v[2 * q + 1][1]);
            dst[q * 32] = o;
        }
    }
}

// ---------------- kernel 2: the GEMM ----------------
#define MMA4(acc, av, b0, b1)                                                   \
    asm volatile(                                                               \
        "mma.sync.aligned.m16n8k8.row.col.f32.tf32.tf32.f32 "                   \
        "{%0,%1,%2,%3}, {%4,%5,%6,%7}, {%8,%9}, {%0,%1,%2,%3};\n"               \
        : "+f"((acc)[0]), "+f"((acc)[1]), "+f"((acc)[2]), "+f"((acc)[3])        \
        : "r"(__float_as_uint((av).x)), "r"(__float_as_uint((av).y)),           \
          "r"(__float_as_uint((av).z)), "r"(__float_as_uint((av).w)),           \
          "r"(__float_as_uint(b0)), "r"(__float_as_uint(b1)))

#define CPA16(dst, src)                                                         \
    asm volatile("{ .reg .u64 g; cvta.to.global.u64 g, %1;"                     \
                 "  cp.async.cg.shared.global [%0], [g], 16; }"                 \
                 :: "r"(dst), "l"(src) : "memory")
#define CP_COMMIT() asm volatile("cp.async.commit_group;" ::: "memory")
#define CP_WAIT3()  asm volatile("cp.async.wait_group 3;" ::: "memory")

#define LDS128F(v, addr)                                                        \
    asm volatile("ld.shared.v4.f32 {%0,%1,%2,%3}, [%4];"                        \
                 : "=f"((v).x), "=f"((v).y), "=f"((v).z), "=f"((v).w)           \
                 : "r"(addr))

// issue cp.async copies for pipeline stage i into smem slot (512 threads)
__device__ __forceinline__ void issue_stage(uint32_t sbase, int slot, int i,
                                            int fb, int mb, int b, int tid)
{
    uint32_t sa  = sbase + slot * STAGE_BYTES;
    uint32_t sbB = sa + STAGE_A_BYTES;
    // A: 512 float4 (2 substeps x 8 rb x 32 lane), 1 per thread
    {
        int c    = tid;
        int ss   = c >> 8;
        int rb   = (c >> 5) & 7;
        int lane = c & 31;
        const float4* src = Afrag + ((size_t)(fb * 8 + rb) * NSTEP + (2 * i + ss)) * 32 + lane;
        CPA16(sa + c * 16, src);
    }
    // B: 1024 float4 (2 substeps x 512), 2 per thread
    #pragma unroll
    for (int j = 0; j < 2; j++) {
        int c   = tid + 512 * j;
        int ss  = c >> 9;
        int rem = c & 511;
        const float4* src = Bfrag + ((size_t)((b * NSTEP + 2 * i + ss) * 16 + mb * 4)) * 128 + rem;
        CPA16(sbB + c * 16, src);
    }
}

__global__ void __launch_bounds__(512, 1) hippo_gemm(
    const float* __restrict__ base,
    float*       __restrict__ out)
{
    extern __shared__ char smem_raw[];
    const uint32_t sbase = smem_u32(smem_raw);

    const int tid  = threadIdx.x;
    const int warp = tid >> 5;
    const int lane = tid & 31;
    const int g    = lane >> 2;
    const int tig  = lane & 3;

    const int mb = blockIdx.x;            // 0..3   (256 m per CTA)
    const int fb = blockIdx.y;            // 0..7   (128 freq per CTA)
    const int b  = blockIdx.z;

    const int warp_f = warp & 1;          // 2 freq halves of 64
    const int warp_n = warp >> 1;         // 8 m-chunks of 32
    const int rbg0 = fb * 8 + warp_f * 4; // first 16-row block of this warp

    float acc[4][4][4];                   // 64 regs: 4 rb x 4 col-groups(8) x 4
    #pragma unroll
    for (int rb = 0; rb < 4; rb++)
        #pragma unroll
        for (int j = 0; j < 4; j++)
            #pragma unroll
            for (int c = 0; c < 4; c++) acc[rb][j][c] = 0.f;

    // ---- prologue: fill stages 0..3
    #pragma unroll
    for (int i = 0; i < STAGES - 1; i++) {
        issue_stage(sbase, i, i, fb, mb, b, tid);
        CP_COMMIT();
    }

    // per-warp smem fragment bases (slot-relative)
    const uint32_t a_off = warp_f * 2048 + lane * 16;   // + ss*4096 + rb*512
    const uint32_t b_off = STAGE_A_BYTES
                         + (warp_n >> 1) * 2048         // nb block within stage
                         + (warp_n & 1) * 1024          // q pair
                         + lane * 16;                   // + ss*8192 + q*512

    #pragma unroll 1
    for (int i = 0; i < NITER; i++) {
        CP_WAIT3();            // stage i arrived
        __syncthreads();       // all warps done reading the slot being overwritten

        if (i + STAGES - 1 < NITER)
            issue_stage(sbase, (i + STAGES - 1) % STAGES, i + STAGES - 1, fb, mb, b, tid);
        CP_COMMIT();           // always commit (empty groups complete instantly)

        const uint32_t slot_base = sbase + (i % STAGES) * STAGE_BYTES;

        #pragma unroll
        for (int ss = 0; ss < 2; ss++) {
            float4 ab[4], bq[2];
            uint32_t ab_addr = slot_base + a_off + ss * 4096;
            uint32_t bb_addr = slot_base + b_off + ss * 8192;
            #pragma unroll
            for (int rb = 0; rb < 4; rb++) LDS128F(ab[rb], ab_addr + rb * 512);
            #pragma unroll
            for (int q = 0; q < 2; q++)    LDS128F(bq[q], bb_addr + q * 512);

            #pragma unroll
            for (int rb = 0; rb < 4; rb++)
                #pragma unroll
                for (int j = 0; j < 4; j++) {
                    const float4& bv = bq[j >> 1];
                    if (j & 1) { MMA4(acc[rb][j], ab[rb], bv.z, bv.w); }
                    else       { MMA4(acc[rb][j], ab[rb], bv.x, bv.y); }
                }
        }
    }

    // ---- epilogue: out = base + acc
    const int col0 = mb * 256 + (warp_n >> 1) * 64 + (warp_n & 1) * 32 + tig * 2;
    #pragma unroll
    for (int rb = 0; rb < 4; rb++) {
        int r0 = (rbg0 + rb) * 16 + g;
        size_t off0 = ((size_t)(b * FDIM + r0)) * MDIM + col0;
        size_t off1 = off0 + (size_t)8 * MDIM;
        #pragma unroll
        for (int j = 0; j < 4; j++) {
            size_t o0 = off0 + j * 8;
            size_t o1 = off1 + j * 8;
            float2 b0 = *(const float2*)(base + o0);
            float2 b1 = *(const float2*)(base + o1);
            float2 w0, w1;
            w0.x = b0.x + acc[rb][j][0];
            w0.y = b0.y + acc[rb][j][1];
            w1.x = b1.x + acc[rb][j][2];
            w1.y = b1.y + acc[rb][j][3];
            *(float2*)(out + o0) = w0;
            *(float2*)(out + o1) = w1;
        }
    }
}

// ---------------- host launch ----------------
extern "C" void kernel_launch(void* const* d_in, const int* in_sizes, int n_in,
                              void* d_out, int out_size)
{
    const float* base  = nullptr;
    const float* slice = nullptr;
    const int*   tok   = nullptr;
    for (int i = 0; i < n_in; i++) {
        if      (in_sizes[i] == 4 * 4096 * 1024) slice = (const float*)d_in[i];
        else if (in_sizes[i] == 4 * 1024 * 1024) base  = (const float*)d_in[i];
        else                                     tok   = (const int*)d_in[i];
    }
    if (!base  && n_in > 0) base  = (const float*)d_in[0];
    if (!slice && n_in > 1) slice = (const float*)d_in[1];

    static bool attr_set = false;
    if (!attr_set) {
        cudaFuncSetAttribute(hippo_gemm,
                             cudaFuncAttributeMaxDynamicSharedMemorySize, SMEM_TOTAL);
        attr_set = true;
    }

    prep_kernel<<<8192, 256>>>(tok, slice);

    dim3 grid(4, 8, 4);   // m-blocks(256) x f-blocks(128) x batch = 128 CTAs
    hippo_gemm<<<grid, 512, SMEM_TOTAL>>>(base, (float*)d_out);
}

// round 8
// speedup vs baseline: 1.1226x; 1.0808x over previous
#include <cuda_runtime.h>
#include <cstdint>
#include <cstddef>

// ---------------------------------------------------------------------------
// MultiDimHiPPO2 on sm_100 (non-'a' PTX target: NO tcgen05; legacy mma.sync).
//
//   out[b, f, m] = base[b, f, m] + sum_k T[f,k] * slice[b,k,m]
//   T[f,k] = cos(2pi*(k+tok)*f/8192)        for f in [0,512)
//          = sin(2pi*(k+tok)*(f-512)/8192)  for f in [512,1024)
//
// Operands pre-shuffled into m16n8k8 tf32 fragment order in gmem.
// GEMM: CTA tile 128f x 128m, 256 thr, 2 CTAs/SM (convoy decorrelation),
// 5-stage cp.async smem pipeline, in-register fragment double buffering.
// ---------------------------------------------------------------------------

#define KDIM    4096
#define MDIM    1024
#define FDIM    1024
#define NSTEP   (KDIM / 8)        // 512 k-steps of 8
#define NITER   (NSTEP / 2)       // 256 stages of 16 k
#define STAGES  5
#define STAGE_A_BYTES 8192        // 128 f x 16 k x 4B (frag order)
#define STAGE_B_BYTES 8192        // 128 m x 16 k x 4B (frag order)
#define STAGE_BYTES   (STAGE_A_BYTES + STAGE_B_BYTES)   // 16 KB
#define SMEM_TOTAL    (STAGES * STAGE_BYTES)            // 80 KB per CTA

// A-fragment store:  Afrag[(rb16*512 + s)*32 + lane] = {a0,a1,a2,a3}
__device__ float4 Afrag[64 * NSTEP * 32];                 // 16 MB
// B-fragment store:  Bfrag[(((b*512+s)*16 + nb)*4 + q)*32 + lane]
__device__ float4 Bfrag[4 * NSTEP * 16 * 4 * 32];         // 64 MB

__device__ __forceinline__ uint32_t f2tf32(float x) {
    uint32_t r;
    asm("cvt.rna.tf32.f32 %0, %1;" : "=r"(r) : "f"(x));
    return r;
}
__device__ __forceinline__ float tf32f(float x) {
    return __uint_as_float(f2tf32(x));
}
__device__ __forceinline__ uint32_t smem_u32(const void* p) {
    uint32_t a;
    asm("{ .reg .u64 t; cvta.to.shared.u64 t, %1; cvt.u32.u64 %0, t; }"
        : "=r"(a) : "l"(p));
    return a;
}

// exact integer phase -> trig value (tf32-rounded)
__device__ __forceinline__ float trigval(int k, int tok, int n, bool use_sin) {
    int p = ((k + tok) * n) & 8191;
    if (p >= 4096) p -= 8192;
    float ang = (float)p * (6.28318530718f / 8192.0f);
    float v = use_sin ? __sinf(ang) : __cosf(ang);
    return tf32f(v);
}

// ---------------- kernel 1: merged pre-pass (unchanged, proven) ----------------
__global__ void __launch_bounds__(256) prep_kernel(const int* __restrict__ tokp,
                                                   const float* __restrict__ slice)
{
    if (blockIdx.x < 4096) {
        int t = blockIdx.x * 256 + threadIdx.x;        // 0 .. 1M-1
        int lane = t & 31;
        int s    = (t >> 5) & 511;
        int rb16 = t >> 14;                            // 0..63
        int g   = lane >> 2;
        int tig = lane & 3;
        int token = tokp ? tokp[0] : 1024;

        int f1 = rb16 * 16 + g;
        int f2 = f1 + 8;
        bool use_sin = (f1 >= 512);
        int n1 = f1 & 511;
        int n2 = f2 & 511;
        int k1 = s * 8 + tig;
        int k2 = k1 + 4;

        float4 v;
        v.x = trigval(k1, token, n1, use_sin);
        v.y = trigval(k1, token, n2, use_sin);
        v.z = trigval(k2, token, n1, use_sin);
        v.w = trigval(k2, token, n2, use_sin);
        Afrag[t] = v;
    } else {
        int t = (blockIdx.x - 4096) * 256 + threadIdx.x;  // 0 .. 1M-1
        int lane = t & 31;
        int nb   = (t >> 5) & 15;
        int s    = (t >> 9) & 511;
        int b    = t >> 18;
        int g   = lane >> 2;
        int tig = lane & 3;

        const float* sp = slice + ((size_t)b * KDIM) * MDIM + nb * 64 + g;
        float v[8][2];
        #pragma unroll
        for (int h = 0; h < 2; h++) {
            int k = s * 8 + tig + 4 * h;
            const float* rp = sp + (size_t)k * MDIM;
            #pragma unroll
            for (int j = 0; j < 8; j++) v[j][h] = rp[j * 8];
        }
        float4* dst = Bfrag + ((size_t)((b * 512 + s) * 16 + nb) * 4) * 32 + lane;
        #pragma unroll
        for (int q = 0; q < 4; q++) {
            float4 o;
            o.x = tf32f(v[2 * q    ][0]);
            o.y = tf32f(v[2 * q    ][1]);
            o.z = tf32f(v[2 * q + 1][0]);
            o.w = tf32f(v[2 * q + 1][1]);
            dst[q * 32] = o;
        }
    }
}

// ---------------- kernel 2: the GEMM ----------------
#define MMA4(acc, av, b0, b1)                                                   \
    asm volatile(                                                               \
        "mma.sync.aligned.m16n8k8.row.col.f32.tf32.tf32.f32 "                   \
        "{%0,%1,%2,%3}, {%4,%5,%6,%7}, {%8,%9}, {%0,%1,%2,%3};\n"               \
        : "+f"((acc)[0]), "+f"((acc)[1]), "+f"((acc)[2]), "+f"((acc)[3])        \
        : "r"(__float_as_uint((av).x)), "r"(__float_as_uint((av).y)),           \
          "r"(__float_as_uint((av).z)), "r"(__float_as_uint((av).w)),           \
          "r"(__float_as_uint(b0)), "r"(__float_as_uint(b1)))

#define CPA16(dst, src)                                                         \
    asm volatile("{ .reg .u64 g; cvta.to.global.u64 g, %1;"                     \
                 "  cp.async.cg.shared.global [%0], [g], 16; }"                 \
                 :: "r"(dst), "l"(src) : "memory")
#define CP_COMMIT() asm volatile("cp.async.commit_group;" ::: "memory")
#define CP_WAIT3()  asm volatile("cp.async.wait_group 3;" ::: "memory")

#define LDS128F(v, addr)                                                        \
    asm volatile("ld.shared.v4.f32 {%0,%1,%2,%3}, [%4];"                        \
                 : "=f"((v).x), "=f"((v).y), "=f"((v).z), "=f"((v).w)           \
                 : "r"(addr))

// issue cp.async copies for pipeline stage i into smem slot (256 threads)
__device__ __forceinline__ void issue_stage(uint32_t sbase, int slot, int i,
                                            int fb, int mb, int b, int tid)
{
    uint32_t sa  = sbase + slot * STAGE_BYTES;
    uint32_t sbB = sa + STAGE_A_BYTES;
    // A: 512 float4 (2 ss x 8 rb x 32 lane), 2 per thread
    #pragma unroll
    for (int j = 0; j < 2; j++) {
        int c    = tid + 256 * j;
        int ss   = c >> 8;
        int rb   = (c >> 5) & 7;
        int lane = c & 31;
        const float4* src = Afrag + ((size_t)(fb * 8 + rb) * NSTEP + (2 * i + ss)) * 32 + lane;
        CPA16(sa + c * 16, src);
    }
    // B: 512 float4 (2 ss x 2 nb_local x 4 q x 32 lane), 2 per thread
    #pragma unroll
    for (int j = 0; j < 2; j++) {
        int c   = tid + 256 * j;
        int ss  = c >> 8;
        int rem = c & 255;
        int nbl = rem >> 7;            // 0..1
        int q   = (rem >> 5) & 3;
        int lane = c & 31;
        const float4* src = Bfrag +
            ((size_t)(((b * NSTEP + 2 * i + ss) * 16 + (mb * 2 + nbl)) * 4 + q)) * 32 + lane;
        CPA16(sbB + c * 16, src);
    }
}

__global__ void __launch_bounds__(256, 2) hippo_gemm(
    const float* __restrict__ base,
    float*       __restrict__ out)
{
    extern __shared__ char smem_raw[];
    const uint32_t sbase = smem_u32(smem_raw);

    const int tid  = threadIdx.x;
    const int warp = tid >> 5;
    const int lane = tid & 31;
    const int g    = lane >> 2;
    const int tig  = lane & 3;

    const int mb = blockIdx.x;            // 0..7   (128 m per CTA)
    const int fb = blockIdx.y;            // 0..7   (128 freq per CTA)
    const int b  = blockIdx.z;

    const int warp_f = warp & 1;          // 2 freq halves of 64
    const int warp_n = warp >> 1;         // 4 m-chunks of 32
    const int rbg0 = fb * 8 + warp_f * 4; // first 16-row block of this warp

    float acc[4][4][4];                   // 64 regs
    #pragma unroll
    for (int rb = 0; rb < 4; rb++)
        #pragma unroll
        for (int j = 0; j < 4; j++)
            #pragma unroll
            for (int c = 0; c < 4; c++) acc[rb][j][c] = 0.f;

    // ---- prologue: fill stages 0..3
    #pragma unroll
    for (int i = 0; i < STAGES - 1; i++) {
        issue_stage(sbase, i, i, fb, mb, b, tid);
        CP_COMMIT();
    }

    // per-warp smem fragment bases (slot-relative)
    const uint32_t a_off = warp_f * 2048 + lane * 16;   // + ss*4096 + rbi*512
    const uint32_t b_off = STAGE_A_BYTES
                         + (warp_n >> 1) * 2048         // nb_local
                         + (warp_n & 1) * 1024          // q pair
                         + lane * 16;                   // + ss*4096 + q*512

    #pragma unroll 1
    for (int i = 0; i < NITER; i++) {
        CP_WAIT3();            // stage i arrived
        __syncthreads();       // all warps done reading the slot being overwritten

        if (i + STAGES - 1 < NITER)
            issue_stage(sbase, (i + STAGES - 1) % STAGES, i + STAGES - 1, fb, mb, b, tid);
        CP_COMMIT();           // always commit (empty groups complete instantly)

        const uint32_t slot_base = sbase + (i % STAGES) * STAGE_BYTES;

        // load ALL fragments for both substeps, then run both MMA batches
        float4 aF[2][4], bF[2][2];
        #pragma unroll
        for (int ss = 0; ss < 2; ss++) {
            uint32_t aa = slot_base + a_off + ss * 4096;
            uint32_t ba = slot_base + b_off + ss * 4096;
            #pragma unroll
            for (int rb = 0; rb < 4; rb++) LDS128F(aF[ss][rb], aa + rb * 512);
            #pragma unroll
            for (int q = 0; q < 2; q++)    LDS128F(bF[ss][q], ba + q * 512);
        }
        #pragma unroll
        for (int ss = 0; ss < 2; ss++) {
            #pragma unroll
            for (int rb = 0; rb < 4; rb++)
                #pragma unroll
                for (int j = 0; j < 4; j++) {
                    const float4& bv = bF[ss][j >> 1];
                    if (j & 1) { MMA4(acc[rb][j], aF[ss][rb], bv.z, bv.w); }
                    else       { MMA4(acc[rb][j], aF[ss][rb], bv.x, bv.y); }
                }
        }
    }

    // ---- epilogue: out = base + acc
    const int col0 = mb * 128 + warp_n * 32 + tig * 2;
    #pragma unroll
    for (int rb = 0; rb < 4; rb++) {
        int r0 = (rbg0 + rb) * 16 + g;
        size_t off0 = ((size_t)(b * FDIM + r0)) * MDIM + col0;
        size_t off1 = off0 + (size_t)8 * MDIM;
        #pragma unroll
        for (int j = 0; j < 4; j++) {
            size_t o0 = off0 + j * 8;
            size_t o1 = off1 + j * 8;
            float2 b0 = *(const float2*)(base + o0);
            float2 b1 = *(const float2*)(base + o1);
            float2 w0, w1;
            w0.x = b0.x + acc[rb][j][0];
            w0.y = b0.y + acc[rb][j][1];
            w1.x = b1.x + acc[rb][j][2];
            w1.y = b1.y + acc[rb][j][3];
            *(float2*)(out + o0) = w0;
            *(float2*)(out + o1) = w1;
        }
    }
}

// ---------------- host launch ----------------
extern "C" void kernel_launch(void* const* d_in, const int* in_sizes, int n_in,
                              void* d_out, int out_size)
{
    const float* base  = nullptr;
    const float* slice = nullptr;
    const int*   tok   = nullptr;
    for (int i = 0; i < n_in; i++) {
        if      (in_sizes[i] == 4 * 4096 * 1024) slice = (const float*)d_in[i];
        else if (in_sizes[i] == 4 * 1024 * 1024) base  = (const float*)d_in[i];
        else                                     tok   = (const int*)d_in[i];
    }
    if (!base  && n_in > 0) base  = (const float*)d_in[0];
    if (!slice && n_in > 1) slice = (const float*)d_in[1];

    static bool attr_set = false;
    if (!attr_set) {
        cudaFuncSetAttribute(hippo_gemm,
                             cudaFuncAttributeMaxDynamicSharedMemorySize, SMEM_TOTAL);
        attr_set = true;
    }

    prep_kernel<<<8192, 256>>>(tok, slice);

    dim3 grid(8, 8, 4);   // m-blocks(128) x f-blocks(128) x batch = 256 CTAs
    hippo_gemm<<<grid, 256, SMEM_TOTAL>>>(base, (float*)d_out);
}

// round 9
// speedup vs baseline: 2.0580x; 1.8332x over previous
#include <cuda_runtime.h>
#include <cuda_fp16.h>
#include <cstdint>
#include <cstddef>

// ---------------------------------------------------------------------------
// MultiDimHiPPO2 on sm_100 (non-'a' PTX target: NO tcgen05; legacy mma.sync).
//
//   out[b, f, m] = base[b, f, m] + sum_k T[f,k] * slice[b,k,m]
//   T[f,k] = cos(2pi*(k+tok)*f/8192)        for f in [0,512)
//          = sin(2pi*(k+tok)*(f-512)/8192)  for f in [512,1024)
//
// fp16 m16n8k16 MMA with f32 accumulate: fp16 mantissa == tf32 mantissa
// (10 bits), so precision matches the tf32 version, at 2x tensor rate and
// half the operand traffic. Operands pre-shuffled into exact fragment order.
// GEMM: CTA 128f x 128m, 256 thr, 2 CTAs/SM, 5-stage cp.async pipeline.
// ---------------------------------------------------------------------------

#define KDIM    4096
#define MDIM    1024
#define FDIM    1024
#define NKS     (KDIM / 16)       // 256 k-steps of 16
#define NITER   (NKS / 2)         // 128 stages of 32 k
#define STAGES  5
#define STAGE_A_BYTES 8192        // 128 f x 32 k x 2B (frag order)
#define STAGE_B_BYTES 8192        // 128 m x 32 k x 2B (frag order)
#define STAGE_BYTES   (STAGE_A_BYTES + STAGE_B_BYTES)   // 16 KB
#define SMEM_TOTAL    (STAGES * STAGE_BYTES)            // 80 KB per CTA

// A-frag: AfragH[(rb16*256 + s)*32 + lane] = uint4{a0,a1,a2,a3} (half2 each)
//   a0={T[f1][k0],T[f1][k0+1]} a1={T[f2][k0],T[f2][k0+1]}
//   a2={T[f1][k0+8],T[f1][k0+9]} a3={T[f2][k0+8],T[f2][k0+9]}
//   f1=rb16*16+g, f2=f1+8, k0=s*16+2*tig
__device__ uint4 AfragH[64 * NKS * 32];                  // 8 MB
// B-frag: BfragH[(((b*256+s)*32 + c)*2 + q)*32 + lane] = uint4{b0A,b1A,b0B,b1B}
//   mA=c*32+(2q)*8+g, mB=mA+8; b0={S[k0+2t][m],S[k0+2t+1][m]}, b1=+8 rows
__device__ uint4 BfragH[4 * NKS * 32 * 2 * 32];          // 32 MB

__device__ __forceinline__ uint32_t smem_u32(const void* p) {
    uint32_t a;
    asm("{ .reg .u64 t; cvta.to.shared.u64 t, %1; cvt.u32.u64 %0, t; }"
        : "=r"(a) : "l"(p));
    return a;
}

// exact integer phase -> trig value
__device__ __forceinline__ float trigvalf(int k, int tok, int n, bool use_sin) {
    int p = ((k + tok) * n) & 8191;
    if (p >= 4096) p -= 8192;
    float ang = (float)p * (6.28318530718f / 8192.0f);
    return use_sin ? __sinf(ang) : __cosf(ang);
}
__device__ __forceinline__ uint32_t pack_h2(float lo, float hi) {
    __half2 h = __floats2half2_rn(lo, hi);
    return *reinterpret_cast<uint32_t*>(&h);
}

// ---------------- kernel 1: merged pre-pass ----------------
// blocks [0,2048): trig A-frags (512K uint4).  [2048,10240): slice B-frags (2M uint4)
__global__ void __launch_bounds__(256) prep_kernel(const int* __restrict__ tokp,
                                                   const float* __restrict__ slice)
{
    if (blockIdx.x < 2048) {
        int t = blockIdx.x * 256 + threadIdx.x;        // 0 .. 512K-1
        int lane = t & 31;
        int s    = (t >> 5) & 255;
        int rb16 = t >> 13;                            // 0..63
        int g   = lane >> 2;
        int tig = lane & 3;
        int token = tokp ? tokp[0] : 1024;

        int f1 = rb16 * 16 + g;
        int f2 = f1 + 8;
        bool use_sin = (f1 >= 512);
        int n1 = f1 & 511;
        int n2 = f2 & 511;
        int k0 = s * 16 + 2 * tig;

        uint4 v;
        v.x = pack_h2(trigvalf(k0,     token, n1, use_sin), trigvalf(k0 + 1, token, n1, use_sin));
        v.y = pack_h2(trigvalf(k0,     token, n2, use_sin), trigvalf(k0 + 1, token, n2, use_sin));
        v.z = pack_h2(trigvalf(k0 + 8, token, n1, use_sin), trigvalf(k0 + 9, token, n1, use_sin));
        v.w = pack_h2(trigvalf(k0 + 8, token, n2, use_sin), trigvalf(k0 + 9, token, n2, use_sin));
        AfragH[t] = v;
    } else {
        int t = (blockIdx.x - 2048) * 256 + threadIdx.x;  // 0 .. 2M-1
        int lane = t & 31;
        int q    = (t >> 5) & 1;
        int c    = (t >> 6) & 31;
        int s    = (t >> 11) & 255;
        int b    = t >> 19;
        int g   = lane >> 2;
        int tig = lane & 3;

        int k0 = s * 16 + 2 * tig;
        int mA = c * 32 + (2 * q) * 8 + g;
        int mB = mA + 8;

        const float* sp = slice + (size_t)b * KDIM * MDIM;
        const float* r0 = sp + (size_t)k0 * MDIM;
        const float* r1 = sp + (size_t)(k0 + 1) * MDIM;
        const float* r8 = sp + (size_t)(k0 + 8) * MDIM;
        const float* r9 = sp + (size_t)(k0 + 9) * MDIM;

        uint4 v;
        v.x = pack_h2(r0[mA], r1[mA]);
        v.y = pack_h2(r8[mA], r9[mA]);
        v.z = pack_h2(r0[mB], r1[mB]);
        v.w = pack_h2(r8[mB], r9[mB]);
        BfragH[t] = v;
    }
}

// ---------------- kernel 2: the GEMM ----------------
#define MMAH(acc, av, b0, b1)                                                   \
    asm volatile(                                                               \
        "mma.sync.aligned.m16n8k16.row.col.f32.f16.f16.f32 "                    \
        "{%0,%1,%2,%3}, {%4,%5,%6,%7}, {%8,%9}, {%0,%1,%2,%3};\n"               \
        : "+f"((acc)[0]), "+f"((acc)[1]), "+f"((acc)[2]), "+f"((acc)[3])        \
        : "r"((av).x), "r"((av).y), "r"((av).z), "r"((av).w),                   \
          "r"(b0), "r"(b1))

#define CPA16(dst, src)                                                         \
    asm volatile("{ .reg .u64 g; cvta.to.global.u64 g, %1;"                     \
                 "  cp.async.cg.shared.global [%0], [g], 16; }"                 \
                 :: "r"(dst), "l"(src) : "memory")
#define CP_COMMIT() asm volatile("cp.async.commit_group;" ::: "memory")
#define CP_WAIT3()  asm volatile("cp.async.wait_group 3;" ::: "memory")

#define LDS128U(v, addr)                                                        \
    asm volatile("ld.shared.v4.u32 {%0,%1,%2,%3}, [%4];"                        \
                 : "=r"((v).x), "=r"((v).y), "=r"((v).z), "=r"((v).w)           \
                 : "r"(addr))

// issue cp.async copies for pipeline stage i into smem slot (256 threads)
__device__ __forceinline__ void issue_stage(uint32_t sbase, int slot, int i,
                                            int fb, int mb, int b, int tid)
{
    uint32_t sa  = sbase + slot * STAGE_BYTES;
    uint32_t sbB = sa + STAGE_A_BYTES;
    // A: 512 uint4 ([ss:2][rb:8][lane:32]), 2 per thread
    #pragma unroll
    for (int j = 0; j < 2; j++) {
        int c    = tid + 256 * j;
        int ss   = c >> 8;
        int rem  = c & 255;
        int rb   = rem >> 5;
        int lane = c & 31;
        const uint4* src = AfragH + ((size_t)(fb * 8 + rb) * NKS + (2 * i + ss)) * 32 + lane;
        CPA16(sa + c * 16, src);
    }
    // B: 512 uint4 ([ss:2][cl:4][q:2][lane:32]), 2 per thread
    #pragma unroll
    for (int j = 0; j < 2; j++) {
        int c    = tid + 256 * j;
        int ss   = c >> 8;
        int rem  = c & 255;
        int cl   = rem >> 6;
        int q    = (rem >> 5) & 1;
        int lane = c & 31;
        const uint4* src = BfragH +
            (((size_t)(b * NKS + 2 * i + ss) * 32 + (mb * 4 + cl)) * 2 + q) * 32 + lane;
        CPA16(sbB + c * 16, src);
    }
}

__global__ void __launch_bounds__(256, 2) hippo_gemm(
    const float* __restrict__ base,
    float*       __restrict__ out)
{
    extern __shared__ char smem_raw[];
    const uint32_t sbase = smem_u32(smem_raw);

    const int tid  = threadIdx.x;
    const int warp = tid >> 5;
    const int lane = tid & 31;
    const int g    = lane >> 2;
    const int tig  = lane & 3;

    const int mb = blockIdx.x;            // 0..7   (128 m per CTA)
    const int fb = blockIdx.y;            // 0..7   (128 freq per CTA)
    const int b  = blockIdx.z;

    const int warp_f = warp & 1;          // 2 freq halves of 64
    const int warp_n = warp >> 1;         // 4 m-chunks of 32
    const int rbg0 = fb * 8 + warp_f * 4; // first 16-row block of this warp

    float acc[4][4][4];                   // 64 regs
    #pragma unroll
    for (int rb = 0; rb < 4; rb++)
        #pragma unroll
        for (int j = 0; j < 4; j++)
            #pragma unroll
            for (int c = 0; c < 4; c++) acc[rb][j][c] = 0.f;

    // ---- prologue: fill stages 0..3
    #pragma unroll
    for (int i = 0; i < STAGES - 1; i++) {
        issue_stage(sbase, i, i, fb, mb, b, tid);
        CP_COMMIT();
    }

    // per-warp smem fragment bases (slot-relative)
    const uint32_t a_off = warp_f * 2048 + lane * 16;   // + ss*4096 + rbi*512
    const uint32_t b_off = STAGE_A_BYTES + warp_n * 1024 + lane * 16; // + ss*4096 + q*512

    #pragma unroll 1
    for (int i = 0; i < NITER; i++) {
        CP_WAIT3();            // stage i arrived
        __syncthreads();       // all warps done reading the slot being overwritten

        if (i + STAGES - 1 < NITER)
            issue_stage(sbase, (i + STAGES - 1) % STAGES, i + STAGES - 1, fb, mb, b, tid);
        CP_COMMIT();           // always commit (empty groups complete instantly)

        const uint32_t slot_base = sbase + (i % STAGES) * STAGE_BYTES;

        // load ALL fragments for both k-substeps, then run both MMA batches
        uint4 aF[2][4], bF[2][2];
        #pragma unroll
        for (int ss = 0; ss < 2; ss++) {
            uint32_t aa = slot_base + a_off + ss * 4096;
            uint32_t ba = slot_base + b_off + ss * 4096;
            #pragma unroll
            for (int rb = 0; rb < 4; rb++) LDS128U(aF[ss][rb], aa + rb * 512);
            #pragma unroll
            for (int q = 0; q < 2; q++)    LDS128U(bF[ss][q], ba + q * 512);
        }
        #pragma unroll
        for (int ss = 0; ss < 2; ss++) {
            #pragma unroll
            for (int rb = 0; rb < 4; rb++) {
                MMAH(acc[rb][0], aF[ss][rb], bF[ss][0].x, bF[ss][0].y);
                MMAH(acc[rb][1], aF[ss][rb], bF[ss][0].z, bF[ss][0].w);
                MMAH(acc[rb][2], aF[ss][rb], bF[ss][1].x, bF[ss][1].y);
                MMAH(acc[rb][3], aF[ss][rb], bF[ss][1].z, bF[ss][1].w);
            }
        }
    }

    // ---- epilogue: out = base + acc
    const int col0 = mb * 128 + warp_n * 32 + tig * 2;
    #pragma unroll
    for (int rb = 0; rb < 4; rb++) {
        int r0 = (rbg0 + rb) * 16 + g;
        size_t off0 = ((size_t)(b * FDIM + r0)) * MDIM + col0;
        size_t off1 = off0 + (size_t)8 * MDIM;
        #pragma unroll
        for (int j = 0; j < 4; j++) {
            size_t o0 = off0 + j * 8;
            size_t o1 = off1 + j * 8;
            float2 b0 = *(const float2*)(base + o0);
            float2 b1 = *(const float2*)(base + o1);
            float2 w0, w1;
            w0.x = b0.x + acc[rb][j][0];
            w0.y = b0.y + acc[rb][j][1];
            w1.x = b1.x + acc[rb][j][2];
            w1.y = b1.y + acc[rb][j][3];
            *(float2*)(out + o0) = w0;
            *(float2*)(out + o1) = w1;
        }
    }
}

// ---------------- host launch ----------------
extern "C" void kernel_launch(void* const* d_in, const int* in_sizes, int n_in,
                              void* d_out, int out_size)
{
    const float* base  = nullptr;
    const float* slice = nullptr;
    const int*   tok   = nullptr;
    for (int i = 0; i < n_in; i++) {
        if      (in_sizes[i] == 4 * 4096 * 1024) slice = (const float*)d_in[i];
        else if (in_sizes[i] == 4 * 1024 * 1024) base  = (const float*)d_in[i];
        else                                     tok   = (const int*)d_in[i];
    }
    if (!base  && n_in > 0) base  = (const float*)d_in[0];
    if (!slice && n_in > 1) slice = (const float*)d_in[1];

    static bool attr_set = false;
    if (!attr_set) {
        cudaFuncSetAttribute(hippo_gemm,
                             cudaFuncAttributeMaxDynamicSharedMemorySize, SMEM_TOTAL);
        attr_set = true;
    }

    prep_kernel<<<10240, 256>>>(tok, slice);

    dim3 grid(8, 8, 4);   // m-blocks(128) x f-blocks(128) x batch = 256 CTAs
    hippo_gemm<<<grid, 256, SMEM_TOTAL>>>(base, (float*)d_out);
}